// round 4
// baseline (speedup 1.0000x reference)
#include <cuda_runtime.h>
#include <cuda_bf16.h>

// s_t table: g_s[t] = (h_t . fcW[0,:], h_t . fcW[1,:]),  t in [0,128)
__device__ float2 g_s[128];
// Monotonic ticket counter: launch k uses tickets [128k,128(k+1)) -> replay-safe.
__device__ unsigned g_tickets;

__device__ __forceinline__ float ex2_(float x) { float y; asm("ex2.approx.f32 %0, %1;" : "=f"(y) : "f"(x)); return y; }
__device__ __forceinline__ float lg2_(float x) { float y; asm("lg2.approx.f32 %0, %1;" : "=f"(y) : "f"(x)); return y; }
__device__ __forceinline__ float tanh_(float x){ float y; asm("tanh.approx.f32 %0, %1;" : "=f"(y) : "f"(x)); return y; }
__device__ __forceinline__ float expf_(float x){ return ex2_(x * 1.44269504f); }

__global__ void __launch_bounds__(256, 1)
qlstm_fused(const int*   __restrict__ x,    // (1024,128)
            const float* __restrict__ qw,   // (4,2,8)
            const float* __restrict__ Wo,   // (4,256,8)
            const float* __restrict__ bo,   // (4,256)
            const float* __restrict__ fcW,  // (2,256)
            const float* __restrict__ fcb,  // (2,)
            float*       __restrict__ out)  // (1024,2)
{
    const int tid  = threadIdx.x;
    const int b    = blockIdx.x;          // block b owns time-step t=b
    const int lane = tid & 31;
    const int wrp  = tid >> 5;            // warp w owns batch row b*8+w

    // Prefetch this block's x slice immediately (row b*8+wrp, t=lane*4..+3);
    // the cold-DRAM latency hides behind stage-1 compute.
    const int row = b * 8 + wrp;
    const int4 px = *(const int4*)(x + row * 128 + lane * 4);

    __shared__ float zeta_s[32];
    __shared__ float zz[32];              // zz[g*8+w] = CNOT-ring Heisenberg Z-product
    __shared__ float red0[8], red1[8];

    // Per-wire <Z>: zeta[g][j] = -sin(qw[g,0,j])  (RX embedding + RZ unobservable)
    if (tid < 32) {
        int g = tid >> 3, j = tid & 7;
        zeta_s[tid] = -sinf(qw[g * 16 + j]);   // precise sinf: off critical mass, cheap
    }
    __syncwarp();
    if (tid < 32) {
        int g = tid >> 3, w = tid & 7;
        float p = 1.0f;
        if (w == 0) { for (int j = 1; j < 8; j++)  p *= zeta_s[g * 8 + j]; }
        else        { for (int j = 0; j <= w; j++) p *= zeta_s[g * 8 + j]; }
        zz[tid] = p;
    }
    __syncthreads();

    // Stage 1: constant gate pre-activations for hidden unit h = tid.
    const int h = tid;
    float pre[4];
#pragma unroll
    for (int g = 0; g < 4; g++) {
        const float4* wp = (const float4*)(Wo + (g * 256 + h) * 8);
        float4 wa = wp[0], wb = wp[1];
        const float* z = &zz[g * 8];
        pre[g] = bo[g * 256 + h]
               + wa.x * z[0] + wa.y * z[1] + wa.z * z[2] + wa.w * z[3]
               + wb.x * z[4] + wb.y * z[5] + wb.z * z[6] + wb.w * z[7];
    }
    // f = sigmoid(pre0); closed-form c_n = ig*(1-f^n)/(1-f), n=b+1.
    // e = exp(-pre0); 1-f = e/(1+e) exactly; f^n = 2^(n*log2 f).
    const float e    = expf_(-pre[0]);
    const float ope  = 1.0f + e;
    const float lf2  = -lg2_(ope);                       // log2(f)
    const float ig   = tanh_(pre[2]) * __frcp_rn(1.0f + expf_(-pre[1]));
    const float oo   = __frcp_rn(1.0f + expf_(-pre[3]));
    const float n    = (float)(b + 1);
    const float fn   = ex2_(n * lf2);                    // f^n
    const float c    = ig * (1.0f - fn) * __fdividef(ope, e);
    const float hv   = oo * tanh_(c);

    // Reduce over h: s0 = sum_h hv*fcW[0,h], s1 = sum_h hv*fcW[1,h]
    float s0 = hv * fcW[h];
    float s1 = hv * fcW[256 + h];
#pragma unroll
    for (int off = 16; off; off >>= 1) {
        s0 += __shfl_xor_sync(0xffffffffu, s0, off);
        s1 += __shfl_xor_sync(0xffffffffu, s1, off);
    }
    if (lane == 0) { red0[wrp] = s0; red1[wrp] = s1; }
    __syncthreads();
    if (tid == 0) {
        float t0 = 0.0f, t1 = 0.0f;
#pragma unroll
        for (int k = 0; k < 8; k++) { t0 += red0[k]; t1 += red1[k]; }
        g_s[b] = make_float2(t0, t1);
        __threadfence();
        unsigned old    = atomicAdd(&g_tickets, 1u);     // single arrival atomic
        unsigned target = ((old >> 7) + 1u) << 7;        // end of this launch's cohort
        unsigned cur;
        do {                                              // cheap non-atomic poll
            asm volatile("ld.global.cg.u32 %0, [%1];" : "=r"(cur) : "l"(&g_tickets));
        } while ((int)(cur - target) < 0);
        __threadfence();                                  // acquire
    }
    __syncthreads();

    // Stage 2: masks (already in regs) x s-table. g_s never touched pre-barrier,
    // L1 flushed per launch -> plain L1-cached vector loads are safe; warps 1-7 hit L1.
    const float4* st = (const float4*)g_s;                // 2 float2 per float4
    float4 sa = st[lane * 2 + 0];                         // s[t], s[t+1]
    float4 sb = st[lane * 2 + 1];                         // s[t+2], s[t+3]
    float a0 = 0.0f, a1 = 0.0f, cnt = 0.0f, m;
    m = (px.x != 0) ? 1.0f : 0.0f; a0 += m * sa.x; a1 += m * sa.y; cnt += m;
    m = (px.y != 0) ? 1.0f : 0.0f; a0 += m * sa.z; a1 += m * sa.w; cnt += m;
    m = (px.z != 0) ? 1.0f : 0.0f; a0 += m * sb.x; a1 += m * sb.y; cnt += m;
    m = (px.w != 0) ? 1.0f : 0.0f; a0 += m * sb.z; a1 += m * sb.w; cnt += m;
#pragma unroll
    for (int off = 16; off; off >>= 1) {
        a0  += __shfl_xor_sync(0xffffffffu, a0, off);
        a1  += __shfl_xor_sync(0xffffffffu, a1, off);
        cnt += __shfl_xor_sync(0xffffffffu, cnt, off);
    }
    if (lane == 0) {
        float inv = __frcp_rn(cnt + 1e-9f);
        float2 o = make_float2(a0 * inv + fcb[0], a1 * inv + fcb[1]);
        *(float2*)(out + row * 2) = o;
    }
}

extern "C" void kernel_launch(void* const* d_in, const int* in_sizes, int n_in,
                              void* d_out, int out_size)
{
    // metadata order: x, embed, Wi, bi, qw, Wo, bo, fcW, fcb
    const int*   x   = (const int*)  d_in[0];
    const float* qw  = (const float*)d_in[4];
    const float* Wo  = (const float*)d_in[5];
    const float* bo  = (const float*)d_in[6];
    const float* fcW = (const float*)d_in[7];
    const float* fcb = (const float*)d_in[8];
    float* out = (float*)d_out;

    qlstm_fused<<<128, 256>>>(x, qw, Wo, bo, fcW, fcb, out);

    (void)in_sizes; (void)n_in; (void)out_size;
}

// round 5
// speedup vs baseline: 1.0058x; 1.0058x over previous
#include <cuda_runtime.h>
#include <cuda_bf16.h>

__device__ __forceinline__ float tanh_(float x){ float y; asm("tanh.approx.f32 %0, %1;" : "=f"(y) : "f"(x)); return y; }
__device__ __forceinline__ float ex2_(float x) { float y; asm("ex2.approx.f32 %0, %1;" : "=f"(y) : "f"(x)); return y; }
__device__ __forceinline__ float sig_(float x) { return __frcp_rn(1.0f + ex2_(-1.44269504f * x)); }

// Fully barrier-free: every block redundantly computes the (input-independent)
// s_t table (t in [0,128), 2 classes) from the analytically-collapsed quantum
// LSTM, then applies it to its own 8 batch rows' padding masks. 128 blocks,
// one per SM, zero inter-block communication.
__global__ void __launch_bounds__(256, 1)
qlstm_all(const int*   __restrict__ x,    // (1024,128)
          const float* __restrict__ qw,   // (4,2,8)
          const float* __restrict__ Wo,   // (4,256,8)
          const float* __restrict__ bo,   // (4,256)
          const float* __restrict__ fcW,  // (2,256)
          const float* __restrict__ fcb,  // (2,)
          float*       __restrict__ out)  // (1024,2)
{
    const int tid  = threadIdx.x;
    const int lane = tid & 31;
    const int wrp  = tid >> 5;
    const int row  = blockIdx.x * 8 + wrp;       // this warp's batch row

    // Prefetch mask slice immediately; cold-DRAM latency hides behind compute.
    const int4 px = *(const int4*)(x + row * 128 + lane * 4);

    __shared__ float zeta_s[32];
    __shared__ float zz[32];                     // CNOT-ring Heisenberg Z-products
    __shared__ float fw0[256], fw1[256];         // fcW rows (smem-hot for phase B)
    __shared__ float hbuf[32][264];              // [t_local][h], stride 264: conflict-free
    __shared__ float2 s_s[128];                  // s_t table

    // fcW -> smem (independent loads, overlap with everything)
    fw0[tid] = fcW[tid];
    fw1[tid] = fcW[256 + tid];

    // Per-wire <Z>: zeta[g][j] = -sin(qw[g,0,j])   (H makes RX a global phase; RZ drops)
    if (tid < 32) {
        int g = tid >> 3, j = tid & 7;
        zeta_s[tid] = -__sinf(qw[g * 16 + j]);
    }
    __syncwarp();
    // z[g][0] = prod_{j=1..7} zeta_j ; z[g][w>=1] = prod_{j=0..w} zeta_j
    if (tid < 32) {
        int g = tid >> 3, w = tid & 7;
        float p = 1.0f;
        if (w == 0) { for (int j = 1; j < 8; j++)  p *= zeta_s[g * 8 + j]; }
        else        { for (int j = 0; j <= w; j++) p *= zeta_s[g * 8 + j]; }
        zz[tid] = p;
    }
    __syncthreads();

    // Constant gate pre-activations for hidden unit h = tid
    const int h = tid;
    float pre[4];
#pragma unroll
    for (int g = 0; g < 4; g++) {
        const float4* wp = (const float4*)(Wo + (g * 256 + h) * 8);
        float4 wa = wp[0], wb = wp[1];
        const float* z = &zz[g * 8];
        pre[g] = bo[g * 256 + h]
               + wa.x * z[0] + wa.y * z[1] + wa.z * z[2] + wa.w * z[3]
               + wb.x * z[4] + wb.y * z[5] + wb.z * z[6] + wb.w * z[7];
    }
    const float f_  = sig_(pre[0]);
    const float ig_ = sig_(pre[1]) * tanh_(pre[2]);
    const float oo_ = sig_(pre[3]);

    // Exact LSTM recursion (c chain = 128 dependent FMAs; tanh off-chain),
    // chunked 32 t's at a time through smem for the h-reduction.
    float c = 0.0f;
    for (int ch = 0; ch < 4; ch++) {
        // Phase A: 32 recursion steps, stash h_t per (t_local, h)
#pragma unroll
        for (int tl = 0; tl < 32; tl++) {
            c = fmaf(f_, c, ig_);
            hbuf[tl][h] = oo_ * tanh_(c);
        }
        __syncthreads();
        // Phase B: 8 threads per t reduce 256 h against fcW rows
        {
            const int tl = tid >> 3, r = tid & 7;
            float s0 = 0.0f, s1 = 0.0f;
#pragma unroll
            for (int k = 0; k < 32; k++) {
                int hh = r + (k << 3);
                float hv = hbuf[tl][hh];
                s0 += hv * fw0[hh];
                s1 += hv * fw1[hh];
            }
#pragma unroll
            for (int off = 4; off; off >>= 1) {
                s0 += __shfl_xor_sync(0xffffffffu, s0, off);
                s1 += __shfl_xor_sync(0xffffffffu, s1, off);
            }
            if (r == 0) s_s[ch * 32 + tl] = make_float2(s0, s1);
        }
        __syncthreads();
    }

    // Stage 2: masks (in regs since kernel start) x local s table (smem).
    const int tb = lane * 4;
    float a0 = 0.0f, a1 = 0.0f, cnt = 0.0f, m;
    m = (px.x != 0) ? 1.0f : 0.0f; a0 += m * s_s[tb + 0].x; a1 += m * s_s[tb + 0].y; cnt += m;
    m = (px.y != 0) ? 1.0f : 0.0f; a0 += m * s_s[tb + 1].x; a1 += m * s_s[tb + 1].y; cnt += m;
    m = (px.z != 0) ? 1.0f : 0.0f; a0 += m * s_s[tb + 2].x; a1 += m * s_s[tb + 2].y; cnt += m;
    m = (px.w != 0) ? 1.0f : 0.0f; a0 += m * s_s[tb + 3].x; a1 += m * s_s[tb + 3].y; cnt += m;
#pragma unroll
    for (int off = 16; off; off >>= 1) {
        a0  += __shfl_xor_sync(0xffffffffu, a0, off);
        a1  += __shfl_xor_sync(0xffffffffu, a1, off);
        cnt += __shfl_xor_sync(0xffffffffu, cnt, off);
    }
    if (lane == 0) {
        float inv = __frcp_rn(cnt + 1e-9f);
        float2 o = make_float2(a0 * inv + fcb[0], a1 * inv + fcb[1]);
        *(float2*)(out + row * 2) = o;
    }
}

extern "C" void kernel_launch(void* const* d_in, const int* in_sizes, int n_in,
                              void* d_out, int out_size)
{
    // metadata order: x, embed, Wi, bi, qw, Wo, bo, fcW, fcb
    const int*   x   = (const int*)  d_in[0];
    const float* qw  = (const float*)d_in[4];
    const float* Wo  = (const float*)d_in[5];
    const float* bo  = (const float*)d_in[6];
    const float* fcW = (const float*)d_in[7];
    const float* fcb = (const float*)d_in[8];
    float* out = (float*)d_out;

    qlstm_all<<<128, 256>>>(x, qw, Wo, bo, fcW, fcb, out);

    (void)in_sizes; (void)n_in; (void)out_size;
}

// round 6
// speedup vs baseline: 1.1133x; 1.1068x over previous
#include <cuda_runtime.h>
#include <cuda_bf16.h>

__device__ __forceinline__ float tanh_(float x){ float y; asm("tanh.approx.f32 %0, %1;" : "=f"(y) : "f"(x)); return y; }
__device__ __forceinline__ float ex2_(float x) { float y; asm("ex2.approx.f32 %0, %1;" : "=f"(y) : "f"(x)); return y; }
__device__ __forceinline__ float lg2_(float x) { float y; asm("lg2.approx.f32 %0, %1;" : "=f"(y) : "f"(x)); return y; }
__device__ __forceinline__ float sig_(float x) { return __frcp_rn(1.0f + ex2_(-1.44269504f * x)); }

// 32 blocks x 1024 threads. Each block redundantly builds the (input-independent)
// s_t table via a register-tiled (t,h) sweep, then applies it to its 32 rows.
__global__ void __launch_bounds__(1024, 1)
qlstm_all(const int*   __restrict__ x,    // (1024,128)
          const float* __restrict__ qw,   // (4,2,8)
          const float* __restrict__ Wo,   // (4,256,8)
          const float* __restrict__ bo,   // (4,256)
          const float* __restrict__ fcW,  // (2,256)
          const float* __restrict__ fcb,  // (2,)
          float*       __restrict__ out)  // (1024,2)
{
    const int tid  = threadIdx.x;
    const int lane = tid & 31;
    const int wrp  = tid >> 5;
    const int row  = blockIdx.x * 32 + wrp;      // this warp's batch row

    // Prefetch mask slice immediately (L2-warm across replays).
    const int4 px = *(const int4*)(x + row * 128 + lane * 4);

    __shared__ float  zeta_s[32];
    __shared__ float  zz[32];                    // CNOT-ring Heisenberg Z-products
    __shared__ float4 pA[256];                   // (f, ig, A=ig/(1-f), log2 f)
    __shared__ float2 pB[256];                   // (oo*fcW0, oo*fcW1)
    __shared__ float  part[32][2][132];          // [h-chunk][class][t] partials
    __shared__ float2 s_s[128];

    // zeta[g][j] = -sin(qw[g,0,j]) (H->RX is a global phase; RZ drops out)
    if (tid < 32) {
        int g = tid >> 3, j = tid & 7;
        zeta_s[tid] = -__sinf(qw[g * 16 + j]);
    }
    __syncwarp();
    if (tid < 32) {
        int g = tid >> 3, w = tid & 7;
        float p = 1.0f;
        if (w == 0) { for (int j = 1; j < 8; j++)  p *= zeta_s[g * 8 + j]; }
        else        { for (int j = 0; j <= w; j++) p *= zeta_s[g * 8 + j]; }
        zz[tid] = p;
    }
    __syncthreads();

    // Per-h constant gate params (threads 0..255)
    if (tid < 256) {
        const int h = tid;
        float pre[4];
#pragma unroll
        for (int g = 0; g < 4; g++) {
            const float4* wp = (const float4*)(Wo + (g * 256 + h) * 8);
            float4 wa = wp[0], wb = wp[1];
            const float* z = &zz[g * 8];
            pre[g] = bo[g * 256 + h]
                   + wa.x * z[0] + wa.y * z[1] + wa.z * z[2] + wa.w * z[3]
                   + wb.x * z[4] + wb.y * z[5] + wb.z * z[6] + wb.w * z[7];
        }
        const float e   = ex2_(-1.44269504f * pre[0]);
        const float ope = 1.0f + e;
        const float f_  = __frcp_rn(ope);            // sigmoid(pre0)
        const float lf2 = -lg2_(ope);                // log2(f)
        const float ig_ = sig_(pre[1]) * tanh_(pre[2]);
        const float oo_ = sig_(pre[3]);
        const float omf = __fdividef(e, ope);        // 1 - f (robust)
        const float A_  = ig_ * __frcp_rn(omf);      // c_inf
        pA[h] = make_float4(f_, ig_, A_, lf2);
        pB[h] = make_float2(oo_ * fcW[h], oo_ * fcW[256 + h]);
    }
    __syncthreads();

    // Register-tiled table sweep: thread (tg=lane, hg=wrp) owns t in [4tg,4tg+4),
    // h in [8hg, 8hg+8). Jump-start c via closed form, then exact recursion.
    {
        const int   tg = lane, hg = wrp;
        const float n0 = (float)(4 * tg);
        float4 a0 = make_float4(0.f, 0.f, 0.f, 0.f);
        float4 a1 = make_float4(0.f, 0.f, 0.f, 0.f);
#pragma unroll
        for (int k = 0; k < 8; k++) {
            const int h = hg * 8 + k;
            const float4 P = pA[h];                  // broadcast LDS.128
            const float2 Q = pB[h];
            float c = P.z - P.z * ex2_(n0 * P.w);    // c_{n0} = A(1 - f^{n0})
            float th;
            c = fmaf(P.x, c, P.y); th = tanh_(c); a0.x += Q.x * th; a1.x += Q.y * th;
            c = fmaf(P.x, c, P.y); th = tanh_(c); a0.y += Q.x * th; a1.y += Q.y * th;
            c = fmaf(P.x, c, P.y); th = tanh_(c); a0.z += Q.x * th; a1.z += Q.y * th;
            c = fmaf(P.x, c, P.y); th = tanh_(c); a0.w += Q.x * th; a1.w += Q.y * th;
        }
        *(float4*)&part[hg][0][4 * tg] = a0;
        *(float4*)&part[hg][1][4 * tg] = a1;
    }
    __syncthreads();

    // Combine 32 h-chunk partials per t: thread (t0 = tid>>3, j = tid&7)
    {
        const int t0 = tid >> 3, j = tid & 7;
        float s0 = part[j][0][t0] + part[j +  8][0][t0]
                 + part[j + 16][0][t0] + part[j + 24][0][t0];
        float s1 = part[j][1][t0] + part[j +  8][1][t0]
                 + part[j + 16][1][t0] + part[j + 24][1][t0];
#pragma unroll
        for (int off = 4; off; off >>= 1) {
            s0 += __shfl_xor_sync(0xffffffffu, s0, off);
            s1 += __shfl_xor_sync(0xffffffffu, s1, off);
        }
        if (j == 0) s_s[t0] = make_float2(s0, s1);
    }
    __syncthreads();

    // Stage 2: masks (in regs since start) x s table.
    const int tb = lane * 4;
    float a0 = 0.0f, a1 = 0.0f, cnt = 0.0f, m;
    m = (px.x != 0) ? 1.0f : 0.0f; a0 += m * s_s[tb + 0].x; a1 += m * s_s[tb + 0].y; cnt += m;
    m = (px.y != 0) ? 1.0f : 0.0f; a0 += m * s_s[tb + 1].x; a1 += m * s_s[tb + 1].y; cnt += m;
    m = (px.z != 0) ? 1.0f : 0.0f; a0 += m * s_s[tb + 2].x; a1 += m * s_s[tb + 2].y; cnt += m;
    m = (px.w != 0) ? 1.0f : 0.0f; a0 += m * s_s[tb + 3].x; a1 += m * s_s[tb + 3].y; cnt += m;
#pragma unroll
    for (int off = 16; off; off >>= 1) {
        a0  += __shfl_xor_sync(0xffffffffu, a0, off);
        a1  += __shfl_xor_sync(0xffffffffu, a1, off);
        cnt += __shfl_xor_sync(0xffffffffu, cnt, off);
    }
    if (lane == 0) {
        float inv = __frcp_rn(cnt + 1e-9f);
        float2 o = make_float2(a0 * inv + fcb[0], a1 * inv + fcb[1]);
        *(float2*)(out + row * 2) = o;
    }
}

extern "C" void kernel_launch(void* const* d_in, const int* in_sizes, int n_in,
                              void* d_out, int out_size)
{
    // metadata order: x, embed, Wi, bi, qw, Wo, bo, fcW, fcb
    const int*   x   = (const int*)  d_in[0];
    const float* qw  = (const float*)d_in[4];
    const float* Wo  = (const float*)d_in[5];
    const float* bo  = (const float*)d_in[6];
    const float* fcW = (const float*)d_in[7];
    const float* fcb = (const float*)d_in[8];
    float* out = (float*)d_out;

    qlstm_all<<<32, 1024>>>(x, qw, Wo, bo, fcW, fcb, out);

    (void)in_sizes; (void)n_in; (void)out_size;
}